// round 3
// baseline (speedup 1.0000x reference)
#include <cuda_runtime.h>
#include <cstdint>
#include <cstddef>

// Problem constants
#define TT   2048      // tokens (B*S)
#define HH   2048      // hidden
#define NE   16        // experts
#define TOPK 6
#define ID   1408      // expert intermediate I
#define I2   2816      // 2*I
#define ISH  2816      // shared intermediate
#define IS2  5632      // 2*ISH
#define NSLOT (TT * TOPK)   // 12288 routed (token,expert) pairs total

// ---------------- scratch (device globals; referenced ONLY in device code) --
// Buffer 1 (138 MB): routed gate_up [NSLOT x I2]; shared gate_up [TT x IS2]
//   aliases its head (shared phase finishes before routed phase writes, stream order).
// Buffer 2 ( 69 MB): routed act [NSLOT x ID]; shared act [TT x ISH] aliases head.
__device__ float g_buf1[(size_t)NSLOT * I2];
__device__ float g_buf2[(size_t)NSLOT * ID];
__device__ int   g_cnt [NE];
__device__ int   g_off [NE];
__device__ int   g_tok [NE * TT];
__device__ float g_wt  [NE * TT];

// ---------------- small kernels --------------------------------------------
__global__ void zero_cnt_kernel() {
    if (threadIdx.x < NE) g_cnt[threadIdx.x] = 0;
}

__global__ void prefix_kernel() {
    if (threadIdx.x == 0) {
        int acc = 0;
        for (int e = 0; e < NE; e++) { g_off[e] = acc; acc += g_cnt[e]; }
    }
}

// One block per token: 16 logits, softmax, top-6, append to expert lists.
__global__ void gate_kernel(const float* __restrict__ x,
                            const float* __restrict__ gw) {
    __shared__ float part[256];
    __shared__ float lg[NE];
    const int t   = blockIdx.x;
    const int tid = threadIdx.x;
    const int e   = tid & 15;
    const int c   = tid >> 4;

    const float* xr = x  + (size_t)t * HH;
    const float* wr = gw + (size_t)e * HH;
    float s = 0.f;
    const int h0 = c * 128;
#pragma unroll 8
    for (int h = h0; h < h0 + 128; h += 4) {
        float4 xv = *(const float4*)(xr + h);
        float4 wv = *(const float4*)(wr + h);
        s += xv.x * wv.x + xv.y * wv.y + xv.z * wv.z + xv.w * wv.w;
    }
    part[tid] = s;
    __syncthreads();
    if (tid < NE) {
        float tot = 0.f;
#pragma unroll
        for (int k = 0; k < 16; k++) tot += part[k * 16 + tid];
        lg[tid] = tot;
    }
    __syncthreads();
    if (tid == 0) {
        float mx = lg[0];
#pragma unroll
        for (int i = 1; i < NE; i++) mx = fmaxf(mx, lg[i]);
        float p[NE];
        float den = 0.f;
#pragma unroll
        for (int i = 0; i < NE; i++) { p[i] = expf(lg[i] - mx); den += p[i]; }
        const float inv = 1.f / den;
#pragma unroll
        for (int i = 0; i < NE; i++) p[i] *= inv;

        bool used[NE];
#pragma unroll
        for (int i = 0; i < NE; i++) used[i] = false;
        for (int j = 0; j < TOPK; j++) {
            int   be = 0;
            float bv = -1.f;
            for (int i = 0; i < NE; i++)
                if (!used[i] && p[i] > bv) { bv = p[i]; be = i; }
            used[be] = true;
            const int slot = atomicAdd(&g_cnt[be], 1);
            g_tok[be * TT + slot] = t;
            g_wt [be * TT + slot] = p[be];
        }
    }
}

// shared: act = silu(g) * u   (reads head of buf1, writes head of buf2)
__global__ void act_shared_kernel() {
    const int t = blockIdx.x;
    const float* row  = g_buf1 + (size_t)t * IS2;
    float*       orow = g_buf2 + (size_t)t * ISH;
    for (int i = threadIdx.x; i < ISH; i += blockDim.x) {
        const float g = row[i];
        const float u = row[i + ISH];
        orow[i] = u * g / (1.f + __expf(-g));
    }
}

// routed: act = silu(g) * u * routing_weight
__global__ void act_routed_kernel() {
    const int e = blockIdx.y;
    const int s = blockIdx.x;
    if (s >= g_cnt[e]) return;
    const float w = g_wt[e * TT + s];
    const size_t base = (size_t)(g_off[e] + s);
    const float* row  = g_buf1 + base * I2;
    float*       orow = g_buf2 + base * ID;
    for (int i = threadIdx.x; i < ID; i += blockDim.x) {
        const float g = row[i];
        const float u = row[i + ID];
        orow[i] = w * u * g / (1.f + __expf(-g));
    }
}

// ---------------- fp32 GEMM core:  C[M,N] = A[M,K] * B[N,K]^T ---------------
// 128x128x8 tiles, 256 threads, 8x8 microtile, double-buffered smem.
template <bool GATHER_A, bool SCATTER_C>
__device__ __forceinline__ void gemm_core(
        const float* __restrict__ A, int lda,
        const float* __restrict__ B, int ldb,
        float* __restrict__ C, int ldc,
        int K, int M, const int* __restrict__ tl) {
    const int m0 = blockIdx.y * 128;
    if (m0 >= M) return;
    const int n0 = blockIdx.x * 128;

    __shared__ float As[2][8][128];
    __shared__ float Bs[2][8][128];

    const int tid = threadIdx.x;
    const int lr = tid >> 1;
    const int lk = (tid & 1) * 4;

    const int  arow = m0 + lr;
    const bool avalid = arow < M;
    const float* aptr = A;  // safe dummy base when !avalid
    if (avalid) {
        const int ar = GATHER_A ? tl[arow] : arow;
        aptr = A + (size_t)ar * lda + lk;
    }
    const float* bptr = B + (size_t)(n0 + lr) * ldb + lk;

    const int ty = tid >> 4;
    const int tx = tid & 15;
    const int r0 = ty * 8;
    const int c0 = tx * 8;

    float4 ra = avalid ? *(const float4*)(aptr) : make_float4(0.f, 0.f, 0.f, 0.f);
    float4 rb = *(const float4*)(bptr);
    As[0][lk + 0][lr] = ra.x; As[0][lk + 1][lr] = ra.y;
    As[0][lk + 2][lr] = ra.z; As[0][lk + 3][lr] = ra.w;
    Bs[0][lk + 0][lr] = rb.x; Bs[0][lk + 1][lr] = rb.y;
    Bs[0][lk + 2][lr] = rb.z; Bs[0][lk + 3][lr] = rb.w;
    __syncthreads();

    float acc[8][8];
#pragma unroll
    for (int i = 0; i < 8; i++)
#pragma unroll
        for (int j = 0; j < 8; j++) acc[i][j] = 0.f;

    const int nk = K >> 3;
    for (int kt = 0; kt < nk; kt++) {
        const int cur = kt & 1;
        const bool more = (kt + 1 < nk);
        if (more) {
            const int k0 = (kt + 1) << 3;
            ra = avalid ? *(const float4*)(aptr + k0) : make_float4(0.f, 0.f, 0.f, 0.f);
            rb = *(const float4*)(bptr + k0);
        }
#pragma unroll
        for (int k = 0; k < 8; k++) {
            float a[8], b[8];
            *(float4*)&a[0] = *(const float4*)&As[cur][k][r0];
            *(float4*)&a[4] = *(const float4*)&As[cur][k][r0 + 4];
            *(float4*)&b[0] = *(const float4*)&Bs[cur][k][c0];
            *(float4*)&b[4] = *(const float4*)&Bs[cur][k][c0 + 4];
#pragma unroll
            for (int i = 0; i < 8; i++)
#pragma unroll
                for (int j = 0; j < 8; j++)
                    acc[i][j] += a[i] * b[j];
        }
        if (more) {
            const int nxt = cur ^ 1;
            As[nxt][lk + 0][lr] = ra.x; As[nxt][lk + 1][lr] = ra.y;
            As[nxt][lk + 2][lr] = ra.z; As[nxt][lk + 3][lr] = ra.w;
            Bs[nxt][lk + 0][lr] = rb.x; Bs[nxt][lk + 1][lr] = rb.y;
            Bs[nxt][lk + 2][lr] = rb.z; Bs[nxt][lk + 3][lr] = rb.w;
            __syncthreads();
        }
    }

#pragma unroll
    for (int i = 0; i < 8; i++) {
        const int r = m0 + r0 + i;
        if (r >= M) break;
        const int crow = SCATTER_C ? tl[r] : r;
        float* cp = C + (size_t)crow * ldc + n0 + c0;
        if (SCATTER_C) {
#pragma unroll
            for (int j = 0; j < 8; j++) atomicAdd(cp + j, acc[i][j]);
        } else {
            *(float4*)(cp)     = make_float4(acc[i][0], acc[i][1], acc[i][2], acc[i][3]);
            *(float4*)(cp + 4) = make_float4(acc[i][4], acc[i][5], acc[i][6], acc[i][7]);
        }
    }
}

// ---------------- GEMM wrappers (scratch bound in device code) --------------
__global__ void __launch_bounds__(256, 2)
gemm_shared1(const float* __restrict__ x, const float* __restrict__ sw1) {
    gemm_core<false, false>(x, HH, sw1, HH, g_buf1, IS2, HH, TT, nullptr);
}

__global__ void __launch_bounds__(256, 2)
gemm_shared2(const float* __restrict__ sw2, float* __restrict__ out) {
    gemm_core<false, false>(g_buf2, ISH, sw2, ISH, out, HH, ISH, TT, nullptr);
}

__global__ void __launch_bounds__(256, 2)
gemm_routed1(const float* __restrict__ x, const float* __restrict__ w1) {
    const int e = blockIdx.z;
    gemm_core<true, false>(
        x, HH,
        w1 + (size_t)e * I2 * HH, HH,
        g_buf1 + (size_t)g_off[e] * I2, I2,
        HH, g_cnt[e], g_tok + e * TT);
}

__global__ void __launch_bounds__(256, 2)
gemm_routed2(const float* __restrict__ w2, float* __restrict__ out) {
    const int e = blockIdx.z;
    gemm_core<false, true>(
        g_buf2 + (size_t)g_off[e] * ID, ID,
        w2 + (size_t)e * HH * ID, ID,
        out, HH,
        ID, g_cnt[e], g_tok + e * TT);
}

// ---------------- launcher: kernel launches ONLY ----------------------------
extern "C" void kernel_launch(void* const* d_in, const int* in_sizes, int n_in,
                              void* d_out, int out_size) {
    const float* x   = (const float*)d_in[0];   // (1,2048,2048)
    const float* gw  = (const float*)d_in[1];   // (16,2048)
    const float* w1  = (const float*)d_in[2];   // (16,2816,2048)
    const float* w2  = (const float*)d_in[3];   // (16,2048,1408)
    const float* sw1 = (const float*)d_in[4];   // (5632,2048)
    const float* sw2 = (const float*)d_in[5];   // (2048,2816)
    float* out = (float*)d_out;                 // (1,2048,2048) fp32
    (void)in_sizes; (void)n_in; (void)out_size;

    // 1) routing
    zero_cnt_kernel<<<1, 32>>>();
    gate_kernel<<<TT, 256>>>(x, gw);
    prefix_kernel<<<1, 32>>>();

    // 2) shared FFN: buf1 = x @ sw1^T -> buf2 = act -> out = buf2 @ sw2^T
    gemm_shared1<<<dim3(IS2 / 128, TT / 128, 1), 256>>>(x, sw1);
    act_shared_kernel<<<TT, 256>>>();
    gemm_shared2<<<dim3(HH / 128, TT / 128, 1), 256>>>(sw2, out);

    // 3) routed: buf1 = gather(x) @ w1^T ; buf2 = w*act ; out += buf2 @ w2^T
    gemm_routed1<<<dim3(I2 / 128, TT / 128, NE), 256>>>(x, w1);
    act_routed_kernel<<<dim3(TT, NE), 256>>>();
    gemm_routed2<<<dim3(HH / 128, TT / 128, NE), 256>>>(w2, out);
}

// round 5
// speedup vs baseline: 2.9045x; 2.9045x over previous
#include <cuda_runtime.h>
#include <cstdint>
#include <cstddef>

// Problem constants
#define TT   2048      // tokens (B*S)
#define HH   2048      // hidden
#define NE   16        // experts
#define TOPK 6
#define ID   1408      // expert intermediate I
#define I2   2816      // 2*I
#define ISH  2816      // shared intermediate
#define IS2  5632      // 2*ISH
#define NSLOT (TT * TOPK)   // 12288 routed (token,expert) pairs

// ---------------- scratch (device globals; referenced ONLY in device code) --
__device__ float g_buf1[(size_t)NSLOT * I2];   // 138 MB
__device__ float g_buf2[(size_t)NSLOT * ID];   //  69 MB
__device__ int   g_cnt [NE];
__device__ int   g_off [NE];
__device__ int   g_tok [NE * TT];
__device__ float g_wt  [NE * TT];

// ---------------- small kernels --------------------------------------------
__global__ void zero_cnt_kernel() {
    if (threadIdx.x < NE) g_cnt[threadIdx.x] = 0;
}

__global__ void prefix_kernel() {
    if (threadIdx.x == 0) {
        int acc = 0;
        for (int e = 0; e < NE; e++) { g_off[e] = acc; acc += g_cnt[e]; }
    }
}

__global__ void gate_kernel(const float* __restrict__ x,
                            const float* __restrict__ gw) {
    __shared__ float part[256];
    __shared__ float lg[NE];
    const int t   = blockIdx.x;
    const int tid = threadIdx.x;
    const int e   = tid & 15;
    const int c   = tid >> 4;

    const float* xr = x  + (size_t)t * HH;
    const float* wr = gw + (size_t)e * HH;
    float s = 0.f;
    const int h0 = c * 128;
#pragma unroll 8
    for (int h = h0; h < h0 + 128; h += 4) {
        float4 xv = *(const float4*)(xr + h);
        float4 wv = *(const float4*)(wr + h);
        s += xv.x * wv.x + xv.y * wv.y + xv.z * wv.z + xv.w * wv.w;
    }
    part[tid] = s;
    __syncthreads();
    if (tid < NE) {
        float tot = 0.f;
#pragma unroll
        for (int k = 0; k < 16; k++) tot += part[k * 16 + tid];
        lg[tid] = tot;
    }
    __syncthreads();
    if (tid == 0) {
        float mx = lg[0];
#pragma unroll
        for (int i = 1; i < NE; i++) mx = fmaxf(mx, lg[i]);
        float p[NE];
        float den = 0.f;
#pragma unroll
        for (int i = 0; i < NE; i++) { p[i] = expf(lg[i] - mx); den += p[i]; }
        const float inv = 1.f / den;
#pragma unroll
        for (int i = 0; i < NE; i++) p[i] *= inv;

        bool used[NE];
#pragma unroll
        for (int i = 0; i < NE; i++) used[i] = false;
        for (int j = 0; j < TOPK; j++) {
            int   be = 0;
            float bv = -1.f;
            for (int i = 0; i < NE; i++)
                if (!used[i] && p[i] > bv) { bv = p[i]; be = i; }
            used[be] = true;
            const int slot = atomicAdd(&g_cnt[be], 1);
            g_tok[be * TT + slot] = t;
            g_wt [be * TT + slot] = p[be];
        }
    }
}

__global__ void act_shared_kernel() {
    const int t = blockIdx.x;
    const float* row  = g_buf1 + (size_t)t * IS2;
    float*       orow = g_buf2 + (size_t)t * ISH;
    for (int i = threadIdx.x; i < ISH; i += blockDim.x) {
        const float g = row[i];
        const float u = row[i + ISH];
        orow[i] = u * g / (1.f + __expf(-g));
    }
}

__global__ void act_routed_kernel() {
    const int e = blockIdx.y;
    const int s = blockIdx.x;
    if (s >= g_cnt[e]) return;
    const float w = g_wt[e * TT + s];
    const size_t base = (size_t)(g_off[e] + s);
    const float* row  = g_buf1 + base * I2;
    float*       orow = g_buf2 + base * ID;
    for (int i = threadIdx.x; i < ID; i += blockDim.x) {
        const float g = row[i];
        const float u = row[i + ID];
        orow[i] = w * u * g / (1.f + __expf(-g));
    }
}

// ---------------- TF32 mma.sync GEMM:  C[M,N] = A[M,K] * B[N,K]^T -----------
// 128x128 block tile, KT=16 double-buffered, 256 thr (8 warps, 2m x 4n),
// warp tile 64x32 via m16n8k8 tf32 mma. Inputs rounded to tf32 with RN
// (cvt.rna) on the LDG->STS path; truncation would bias coherently over K.

__device__ __forceinline__ uint32_t tf32r(float f) {
    uint32_t u;
    asm("cvt.rna.tf32.f32 %0, %1;" : "=r"(u) : "f"(f));
    return u;
}

__device__ __forceinline__ void mma8(float* c, const uint32_t* a, const uint32_t* b) {
    asm volatile(
        "mma.sync.aligned.m16n8k8.row.col.f32.tf32.tf32.f32 "
        "{%0,%1,%2,%3},{%4,%5,%6,%7},{%8,%9},{%0,%1,%2,%3};"
        : "+f"(c[0]), "+f"(c[1]), "+f"(c[2]), "+f"(c[3])
        : "r"(a[0]), "r"(a[1]), "r"(a[2]), "r"(a[3]), "r"(b[0]), "r"(b[1]));
}

#define KT   16
#define PADW 20

template <bool GATHER_A, bool SCATTER_C>
__device__ __forceinline__ void mma_core(
        const float* __restrict__ A, int lda,
        const float* __restrict__ B, int ldb,
        float* __restrict__ C, int ldc,
        int K, int M, const int* __restrict__ tl) {
    const int m0 = blockIdx.y * 128;
    if (m0 >= M) return;
    const int n0 = blockIdx.x * 128;

    __shared__ uint32_t As[2][128][PADW];
    __shared__ uint32_t Bs[2][128][PADW];

    const int tid  = threadIdx.x;
    const int lane = tid & 31;
    const int warp = tid >> 5;
    const int warp_m = (warp & 1) * 64;
    const int warp_n = (warp >> 1) * 32;

    const int lrow = tid >> 2;          // 0..63
    const int lc   = (tid & 3) * 4;     // 0,4,8,12

    const float* aRow0; const float* aRow1;
    const float* bRow0; const float* bRow1;
    bool av0, av1;
    {
        const int r0r = m0 + lrow;
        const int r1r = m0 + lrow + 64;
        av0 = r0r < M;
        av1 = r1r < M;
        int a0 = 0, a1 = 0;
        if (av0) a0 = GATHER_A ? tl[r0r] : r0r;
        if (av1) a1 = GATHER_A ? tl[r1r] : r1r;
        aRow0 = A + (size_t)a0 * lda;
        aRow1 = A + (size_t)a1 * lda;
        bRow0 = B + (size_t)(n0 + lrow) * ldb;
        bRow1 = B + (size_t)(n0 + lrow + 64) * ldb;
    }

    float4 ra0, ra1, rb0, rb1;

#define LDG_TILE(kt)                                                          \
    do {                                                                      \
        const int k0_ = (kt) * KT + lc;                                       \
        ra0 = av0 ? *(const float4*)(aRow0 + k0_)                             \
                  : make_float4(0.f, 0.f, 0.f, 0.f);                          \
        ra1 = av1 ? *(const float4*)(aRow1 + k0_)                             \
                  : make_float4(0.f, 0.f, 0.f, 0.f);                          \
        rb0 = *(const float4*)(bRow0 + k0_);                                  \
        rb1 = *(const float4*)(bRow1 + k0_);                                  \
    } while (0)

#define STS_TILE(buf)                                                         \
    do {                                                                      \
        As[buf][lrow][lc + 0] = tf32r(ra0.x);                                 \
        As[buf][lrow][lc + 1] = tf32r(ra0.y);                                 \
        As[buf][lrow][lc + 2] = tf32r(ra0.z);                                 \
        As[buf][lrow][lc + 3] = tf32r(ra0.w);                                 \
        As[buf][lrow + 64][lc + 0] = tf32r(ra1.x);                            \
        As[buf][lrow + 64][lc + 1] = tf32r(ra1.y);                            \
        As[buf][lrow + 64][lc + 2] = tf32r(ra1.z);                            \
        As[buf][lrow + 64][lc + 3] = tf32r(ra1.w);                            \
        Bs[buf][lrow][lc + 0] = tf32r(rb0.x);                                 \
        Bs[buf][lrow][lc + 1] = tf32r(rb0.y);                                 \
        Bs[buf][lrow][lc + 2] = tf32r(rb0.z);                                 \
        Bs[buf][lrow][lc + 3] = tf32r(rb0.w);                                 \
        Bs[buf][lrow + 64][lc + 0] = tf32r(rb1.x);                            \
        Bs[buf][lrow + 64][lc + 1] = tf32r(rb1.y);                            \
        Bs[buf][lrow + 64][lc + 2] = tf32r(rb1.z);                            \
        Bs[buf][lrow + 64][lc + 3] = tf32r(rb1.w);                            \
    } while (0)

    float acc[4][4][4];
#pragma unroll
    for (int mi = 0; mi < 4; mi++)
#pragma unroll
        for (int ni = 0; ni < 4; ni++)
#pragma unroll
            for (int i = 0; i < 4; i++) acc[mi][ni][i] = 0.f;

    const int q  = lane >> 2;
    const int kb = lane & 3;

    LDG_TILE(0);
    STS_TILE(0);
    __syncthreads();

    const int nkt = K / KT;
    for (int kt = 0; kt < nkt; kt++) {
        const int cur = kt & 1;
        const bool more = (kt + 1 < nkt);
        if (more) LDG_TILE(kt + 1);

#pragma unroll
        for (int ks = 0; ks < KT; ks += 8) {
            uint32_t af[4][4], bf[4][2];
#pragma unroll
            for (int mi = 0; mi < 4; mi++) {
                const int r = warp_m + mi * 16 + q;
                af[mi][0] = As[cur][r    ][ks + kb];
                af[mi][1] = As[cur][r + 8][ks + kb];
                af[mi][2] = As[cur][r    ][ks + kb + 4];
                af[mi][3] = As[cur][r + 8][ks + kb + 4];
            }
#pragma unroll
            for (int ni = 0; ni < 4; ni++) {
                const int r = warp_n + ni * 8 + q;
                bf[ni][0] = Bs[cur][r][ks + kb];
                bf[ni][1] = Bs[cur][r][ks + kb + 4];
            }
#pragma unroll
            for (int mi = 0; mi < 4; mi++)
#pragma unroll
                for (int ni = 0; ni < 4; ni++)
                    mma8(acc[mi][ni], af[mi], bf[ni]);
        }

        if (more) STS_TILE(cur ^ 1);
        __syncthreads();
    }

#pragma unroll
    for (int mi = 0; mi < 4; mi++) {
        const int rlo = m0 + warp_m + mi * 16 + q;
        const int rhi = rlo + 8;
#pragma unroll
        for (int ni = 0; ni < 4; ni++) {
            const int col = n0 + warp_n + ni * 8 + 2 * kb;
            if (rlo < M) {
                const int cr = SCATTER_C ? tl[rlo] : rlo;
                float* cp = C + (size_t)cr * ldc + col;
                if (SCATTER_C) {
                    atomicAdd(cp,     acc[mi][ni][0]);
                    atomicAdd(cp + 1, acc[mi][ni][1]);
                } else {
                    *(float2*)cp = make_float2(acc[mi][ni][0], acc[mi][ni][1]);
                }
            }
            if (rhi < M) {
                const int cr = SCATTER_C ? tl[rhi] : rhi;
                float* cp = C + (size_t)cr * ldc + col;
                if (SCATTER_C) {
                    atomicAdd(cp,     acc[mi][ni][2]);
                    atomicAdd(cp + 1, acc[mi][ni][3]);
                } else {
                    *(float2*)cp = make_float2(acc[mi][ni][2], acc[mi][ni][3]);
                }
            }
        }
    }
#undef LDG_TILE
#undef STS_TILE
}

// ---------------- GEMM wrappers ---------------------------------------------
__global__ void __launch_bounds__(256)
gemm_shared1(const float* __restrict__ x, const float* __restrict__ sw1) {
    mma_core<false, false>(x, HH, sw1, HH, g_buf1, IS2, HH, TT, nullptr);
}

__global__ void __launch_bounds__(256)
gemm_shared2(const float* __restrict__ sw2, float* __restrict__ out) {
    mma_core<false, false>(g_buf2, ISH, sw2, ISH, out, HH, ISH, TT, nullptr);
}

__global__ void __launch_bounds__(256)
gemm_routed1(const float* __restrict__ x, const float* __restrict__ w1) {
    const int e = blockIdx.z;
    mma_core<true, false>(
        x, HH,
        w1 + (size_t)e * I2 * HH, HH,
        g_buf1 + (size_t)g_off[e] * I2, I2,
        HH, g_cnt[e], g_tok + e * TT);
}

__global__ void __launch_bounds__(256)
gemm_routed2(const float* __restrict__ w2, float* __restrict__ out) {
    const int e = blockIdx.z;
    mma_core<false, true>(
        g_buf2 + (size_t)g_off[e] * ID, ID,
        w2 + (size_t)e * HH * ID, ID,
        out, HH,
        ID, g_cnt[e], g_tok + e * TT);
}

// ---------------- launcher: kernel launches ONLY ----------------------------
extern "C" void kernel_launch(void* const* d_in, const int* in_sizes, int n_in,
                              void* d_out, int out_size) {
    const float* x   = (const float*)d_in[0];   // (1,2048,2048)
    const float* gw  = (const float*)d_in[1];   // (16,2048)
    const float* w1  = (const float*)d_in[2];   // (16,2816,2048)
    const float* w2  = (const float*)d_in[3];   // (16,2048,1408)
    const float* sw1 = (const float*)d_in[4];   // (5632,2048)
    const float* sw2 = (const float*)d_in[5];   // (2048,2816)
    float* out = (float*)d_out;                 // (1,2048,2048) fp32
    (void)in_sizes; (void)n_in; (void)out_size;

    // 1) routing
    zero_cnt_kernel<<<1, 32>>>();
    gate_kernel<<<TT, 256>>>(x, gw);
    prefix_kernel<<<1, 32>>>();

    // 2) shared FFN
    gemm_shared1<<<dim3(IS2 / 128, TT / 128, 1), 256>>>(x, sw1);
    act_shared_kernel<<<TT, 256>>>();
    gemm_shared2<<<dim3(HH / 128, TT / 128, 1), 256>>>(sw2, out);

    // 3) routed path
    gemm_routed1<<<dim3(I2 / 128, TT / 128, NE), 256>>>(x, w1);
    act_routed_kernel<<<dim3(TT, NE), 256>>>();
    gemm_routed2<<<dim3(HH / 128, TT / 128, NE), 256>>>(w2, out);
}